// round 4
// baseline (speedup 1.0000x reference)
#include <cuda_runtime.h>
#include <cuda_bf16.h>
#include <math.h>
#include <stdint.h>

// ---------------- problem dims ----------------
#define BDIM 4
#define TDIM 2048
#define DDIM 512
#define EDIM 4
#define CDIM 1024
#define HEDIM 512
#define ODIM 512
#define ECDIM 4096

typedef __nv_bfloat16 bf16;

// ---------------- pre-split operand storage (no cudaMalloc allowed) ----------
__device__ bf16 g_dmT_h[(size_t)BDIM * ECDIM * TDIM];   // dmask^T  [B][EC][T]
__device__ bf16 g_dmT_l[(size_t)BDIM * ECDIM * TDIM];
__device__ bf16 g_cmb_h[(size_t)BDIM * TDIM * ECDIM];   // combine  [B][T][EC]
__device__ bf16 g_cmb_l[(size_t)BDIM * TDIM * ECDIM];
__device__ bf16 g_x_h [(size_t)BDIM * TDIM * DDIM];
__device__ bf16 g_x_l [(size_t)BDIM * TDIM * DDIM];
__device__ bf16 g_w1_h[(size_t)EDIM * DDIM * HEDIM];
__device__ bf16 g_w1_l[(size_t)EDIM * DDIM * HEDIM];
__device__ bf16 g_w2_h[(size_t)EDIM * HEDIM * ODIM];
__device__ bf16 g_w2_l[(size_t)EDIM * HEDIM * ODIM];
__device__ bf16 g_xd_h[(size_t)BDIM * ECDIM * DDIM];
__device__ bf16 g_xd_l[(size_t)BDIM * ECDIM * DDIM];
__device__ bf16 g_h_h [(size_t)BDIM * ECDIM * HEDIM];
__device__ bf16 g_h_l [(size_t)BDIM * ECDIM * HEDIM];
__device__ bf16 g_y_h [(size_t)BDIM * ECDIM * ODIM];
__device__ bf16 g_y_l [(size_t)BDIM * ECDIM * ODIM];

// ---------------- split helpers ----------------
__device__ __forceinline__ void split4(const float4& v, uint2& h, uint2& l) {
    uint32_t ax = __float_as_uint(v.x), ay = __float_as_uint(v.y);
    uint32_t az = __float_as_uint(v.z), aw = __float_as_uint(v.w);
    h.x = (ax >> 16) | (ay & 0xffff0000u);
    h.y = (az >> 16) | (aw & 0xffff0000u);
    float lx = v.x - __uint_as_float(ax & 0xffff0000u);
    float ly = v.y - __uint_as_float(ay & 0xffff0000u);
    float lz = v.z - __uint_as_float(az & 0xffff0000u);
    float lw = v.w - __uint_as_float(aw & 0xffff0000u);
    __nv_bfloat162 p0 = __floats2bfloat162_rn(lx, ly);
    __nv_bfloat162 p1 = __floats2bfloat162_rn(lz, lw);
    l.x = *reinterpret_cast<uint32_t*>(&p0);
    l.y = *reinterpret_cast<uint32_t*>(&p1);
}
__device__ __forceinline__ uint32_t pack_hi2(float a, float b) {
    return (__float_as_uint(a) >> 16) | (__float_as_uint(b) & 0xffff0000u);
}
__device__ __forceinline__ uint32_t pack_lo2(float a, float b) {
    float ra = a - __uint_as_float(__float_as_uint(a) & 0xffff0000u);
    float rb = b - __uint_as_float(__float_as_uint(b) & 0xffff0000u);
    __nv_bfloat162 p = __floats2bfloat162_rn(ra, rb);
    return *reinterpret_cast<uint32_t*>(&p);
}

// ---------------- conversion kernels ----------------
__global__ void split_ew(const float* __restrict__ s, bf16* __restrict__ hi,
                         bf16* __restrict__ lo, long long n4) {
    long long i = (long long)blockIdx.x * blockDim.x + threadIdx.x;
    if (i < n4) {
        float4 v = reinterpret_cast<const float4*>(s)[i];
        uint2 h, l; split4(v, h, l);
        reinterpret_cast<uint2*>(hi)[i] = h;
        reinterpret_cast<uint2*>(lo)[i] = l;
    }
}
// src [R][Cc] per batch -> dst [Cc][R] split (transpose)
__global__ void tr_split(const float* __restrict__ s, bf16* __restrict__ hi,
                         bf16* __restrict__ lo, int R, int Cc) {
    __shared__ float t[32][33];
    const int c0 = blockIdx.x * 32, r0 = blockIdx.y * 32;
    const size_t zoff = (size_t)blockIdx.z * R * Cc;
    const float* S = s + zoff;
    const int tx = threadIdx.x & 31, ty = threadIdx.x >> 5;
#pragma unroll
    for (int i = 0; i < 4; i++) {
        int r = ty + i * 8;
        t[r][tx] = S[(size_t)(r0 + r) * Cc + c0 + tx];
    }
    __syncthreads();
#pragma unroll
    for (int i = 0; i < 4; i++) {
        int r = ty + i * 8;                       // output row = c0 + r
        float v = t[tx][r];                       // = src[r0+tx][c0+r]
        uint32_t b = __float_as_uint(v);
        size_t o = zoff + (size_t)(c0 + r) * R + r0 + tx;
        hi[o] = __ushort_as_bfloat16((uint16_t)(b >> 16));
        float lf = v - __uint_as_float(b & 0xffff0000u);
        lo[o] = __float2bfloat16_rn(lf);
    }
}

// ---------------- GEMM tile config ----------------
constexpr int BM = 128, BN = 128, BK = 32;
constexpr int THREADS = 256;
constexpr int OFF_AHI = 0;
constexpr int OFF_ALO = 8192;
constexpr int OFF_BHI = 16384;
constexpr int OFF_BLO = 24576;
constexpr int STAGE = 32768;
constexpr int STAGES = 4;
constexpr int SMEM_TOTAL = STAGES * STAGE;   // 128 KB

__device__ __forceinline__ int a_off(int m, int kchunk) {   // kchunk 0..3
    return m * 64 + ((kchunk ^ ((m >> 1) & 3)) << 4);
}
__device__ __forceinline__ int b_off(int k, int nchunk) {   // nchunk 0..15
    return k * 256 + ((nchunk ^ (k & 7)) << 4);
}
__device__ __forceinline__ uint32_t smem_u32(const void* p) {
    uint32_t a;
    asm("{ .reg .u64 t; cvta.to.shared.u64 t, %1; cvt.u32.u64 %0, t; }"
        : "=r"(a) : "l"(p));
    return a;
}
__device__ __forceinline__ void ldsm4(uint32_t* r, uint32_t addr) {
    asm volatile("ldmatrix.sync.aligned.m8n8.x4.shared.b16 {%0,%1,%2,%3}, [%4];"
                 : "=r"(r[0]), "=r"(r[1]), "=r"(r[2]), "=r"(r[3]) : "r"(addr));
}
__device__ __forceinline__ void ldsm4t(uint32_t* r, uint32_t addr) {
    asm volatile("ldmatrix.sync.aligned.m8n8.x4.trans.shared.b16 {%0,%1,%2,%3}, [%4];"
                 : "=r"(r[0]), "=r"(r[1]), "=r"(r[2]), "=r"(r[3]) : "r"(addr));
}
__device__ __forceinline__ void mma_bf16(float* d, const uint32_t* a, const uint32_t* b) {
    asm volatile(
        "mma.sync.aligned.m16n8k16.row.col.f32.bf16.bf16.f32 "
        "{%0,%1,%2,%3}, {%4,%5,%6,%7}, {%8,%9}, {%0,%1,%2,%3};"
        : "+f"(d[0]), "+f"(d[1]), "+f"(d[2]), "+f"(d[3])
        : "r"(a[0]), "r"(a[1]), "r"(a[2]), "r"(a[3]), "r"(b[0]), "r"(b[1]));
}
__device__ __forceinline__ void cp16(uint32_t dst, const void* src) {
    asm volatile("cp.async.cg.shared.global [%0], [%1], 16;" :: "r"(dst), "l"(src));
}
__device__ __forceinline__ void cp_commit() {
    asm volatile("cp.async.commit_group;" ::: "memory");
}
__device__ __forceinline__ void cp_wait2() {
    asm volatile("cp.async.wait_group 2;" ::: "memory");
}

// ---------------- main GEMM kernel ----------------
// C(MxN) = A * B with pre-split bf16 hi/lo operands.
// OUTM: 0 = fp32 output, 1 = split bf16 hi/lo output.
template<int OUTM, bool GELU_, bool BIAS_>
__global__ __launch_bounds__(THREADS, 1)
void moe_gemm(const bf16* __restrict__ Ah, const bf16* __restrict__ Al,
              const bf16* __restrict__ Bh, const bf16* __restrict__ Bl,
              float* __restrict__ Cf, bf16* __restrict__ Ch, bf16* __restrict__ Cl,
              const float* __restrict__ biasBase,
              int lda, int ldb, int ldc, int KT,
              long long sA, long long sB, long long sC, int bMod,
              long long sBias, int biasMod)
{
    extern __shared__ char smem[];
    const int tid  = threadIdx.x;
    const int lane = tid & 31;
    const int wid  = tid >> 5;
    const int wm   = (wid & 1) * 64;
    const int wn   = (wid >> 1) * 32;

    const int z = blockIdx.z;
    const long long aoff = (long long)z * sA;
    const long long boff = (long long)(bMod ? (z % bMod) : z) * sB;
    const long long coff = (long long)z * sC;
    const float* bias = BIAS_
        ? biasBase + (long long)(biasMod ? (z % biasMod) : z) * sBias : nullptr;

    const int m0 = blockIdx.y * BM;
    const int n0 = blockIdx.x * BN;
    const uint32_t sbase = smem_u32(smem);

    const bf16* pAh = Ah + aoff; const bf16* pAl = Al + aoff;
    const bf16* pBh = Bh + boff; const bf16* pBl = Bl + boff;

    float acc[4][4][4];
#pragma unroll
    for (int i = 0; i < 4; i++)
#pragma unroll
        for (int j = 0; j < 4; j++)
#pragma unroll
            for (int c = 0; c < 4; c++) acc[i][j][c] = 0.f;

    // issue one stage of cp.async (empty commit if past end)
    auto issue = [&](int it) {
        if (it < KT) {
            const uint32_t st = sbase + (it & (STAGES - 1)) * STAGE;
            const int k0 = it * BK;
#pragma unroll
            for (int i = 0; i < 2; i++) {
                int c = tid + i * THREADS;          // 0..511
                int m = c >> 2, kc = c & 3;
                size_t g = (size_t)(m0 + m) * lda + k0 + kc * 8;
                cp16(st + OFF_AHI + a_off(m, kc), pAh + g);
                cp16(st + OFF_ALO + a_off(m, kc), pAl + g);
            }
#pragma unroll
            for (int i = 0; i < 2; i++) {
                int c = tid + i * THREADS;
                int k = c >> 4, nc = c & 15;
                size_t g = (size_t)(k0 + k) * ldb + n0 + nc * 8;
                cp16(st + OFF_BHI + b_off(k, nc), pBh + g);
                cp16(st + OFF_BLO + b_off(k, nc), pBl + g);
            }
        }
        cp_commit();
    };

    issue(0); issue(1); issue(2);

    for (int it = 0; it < KT; ++it) {
        cp_wait2();
        __syncthreads();
        issue(it + 3);

        const uint32_t cur = sbase + (it & (STAGES - 1)) * STAGE;
#pragma unroll
        for (int kh = 0; kh < 2; kh++) {
            uint32_t ahr[4][4], alr[4][4];
#pragma unroll
            for (int mf = 0; mf < 4; mf++) {
                int row = wm + mf * 16 + (lane & 15);
                int chunk = kh * 2 + (lane >> 4);
                int off = a_off(row, chunk);
                ldsm4(ahr[mf], cur + OFF_AHI + off);
                ldsm4(alr[mf], cur + OFF_ALO + off);
            }
            uint32_t bhr[2][4], blr[2][4];
#pragma unroll
            for (int half = 0; half < 2; half++) {
                int k = kh * 16 + ((lane >> 3) & 1) * 8 + (lane & 7);
                int nchunk = ((wn + half * 16) >> 3) + (lane >> 4);
                int off = b_off(k, nchunk);
                ldsm4t(bhr[half], cur + OFF_BHI + off);
                ldsm4t(blr[half], cur + OFF_BLO + off);
            }
#pragma unroll
            for (int mf = 0; mf < 4; mf++)
#pragma unroll
                for (int nf = 0; nf < 4; nf++) {
                    const uint32_t* bhf = &bhr[nf >> 1][(nf & 1) * 2];
                    const uint32_t* blf = &blr[nf >> 1][(nf & 1) * 2];
                    mma_bf16(acc[mf][nf], ahr[mf], bhf);
                    mma_bf16(acc[mf][nf], ahr[mf], blf);
                    mma_bf16(acc[mf][nf], alr[mf], bhf);
                }
        }
    }

    // ---- epilogue ----
    const int g = lane >> 2, t = lane & 3;
#pragma unroll
    for (int mf = 0; mf < 4; mf++) {
#pragma unroll
        for (int nf = 0; nf < 4; nf++) {
            int row = m0 + wm + mf * 16 + g;
            int col = n0 + wn + nf * 8 + t * 2;
            float v0 = acc[mf][nf][0], v1 = acc[mf][nf][1];
            float v2 = acc[mf][nf][2], v3 = acc[mf][nf][3];
            if (BIAS_) {
                float2 bv = *reinterpret_cast<const float2*>(bias + col);
                v0 += bv.x; v1 += bv.y; v2 += bv.x; v3 += bv.y;
            }
            if (GELU_) {
                v0 = 0.5f * v0 * (1.0f + erff(v0 * 0.70710678118654752f));
                v1 = 0.5f * v1 * (1.0f + erff(v1 * 0.70710678118654752f));
                v2 = 0.5f * v2 * (1.0f + erff(v2 * 0.70710678118654752f));
                v3 = 0.5f * v3 * (1.0f + erff(v3 * 0.70710678118654752f));
            }
            if (OUTM == 0) {
                *reinterpret_cast<float2*>(Cf + coff + (size_t)row * ldc + col) =
                    make_float2(v0, v1);
                *reinterpret_cast<float2*>(Cf + coff + (size_t)(row + 8) * ldc + col) =
                    make_float2(v2, v3);
            } else {
                size_t o0 = (size_t)(coff + (size_t)row * ldc + col);
                size_t o1 = (size_t)(coff + (size_t)(row + 8) * ldc + col);
                *reinterpret_cast<uint32_t*>(Ch + o0) = pack_hi2(v0, v1);
                *reinterpret_cast<uint32_t*>(Cl + o0) = pack_lo2(v0, v1);
                *reinterpret_cast<uint32_t*>(Ch + o1) = pack_hi2(v2, v3);
                *reinterpret_cast<uint32_t*>(Cl + o1) = pack_lo2(v2, v3);
            }
        }
    }
}

// ---------------- launcher ----------------
extern "C" void kernel_launch(void* const* d_in, const int* in_sizes, int n_in,
                              void* d_out, int out_size)
{
    const float* x     = (const float*)d_in[0];
    const float* dmask = (const float*)d_in[1];
    const float* comb  = (const float*)d_in[2];
    const float* w1    = (const float*)d_in[3];
    const float* b1    = (const float*)d_in[4];
    const float* w2    = (const float*)d_in[5];
    const float* b2    = (const float*)d_in[6];
    float* out = (float*)d_out;

    bf16 *dmT_h, *dmT_l, *cmb_h, *cmb_l, *x_h, *x_l, *w1_h, *w1_l, *w2_h, *w2_l;
    bf16 *xd_h, *xd_l, *h_h, *h_l, *y_h, *y_l;
    cudaGetSymbolAddress((void**)&dmT_h, g_dmT_h);
    cudaGetSymbolAddress((void**)&dmT_l, g_dmT_l);
    cudaGetSymbolAddress((void**)&cmb_h, g_cmb_h);
    cudaGetSymbolAddress((void**)&cmb_l, g_cmb_l);
    cudaGetSymbolAddress((void**)&x_h,  g_x_h);
    cudaGetSymbolAddress((void**)&x_l,  g_x_l);
    cudaGetSymbolAddress((void**)&w1_h, g_w1_h);
    cudaGetSymbolAddress((void**)&w1_l, g_w1_l);
    cudaGetSymbolAddress((void**)&w2_h, g_w2_h);
    cudaGetSymbolAddress((void**)&w2_l, g_w2_l);
    cudaGetSymbolAddress((void**)&xd_h, g_xd_h);
    cudaGetSymbolAddress((void**)&xd_l, g_xd_l);
    cudaGetSymbolAddress((void**)&h_h,  g_h_h);
    cudaGetSymbolAddress((void**)&h_l,  g_h_l);
    cudaGetSymbolAddress((void**)&y_h,  g_y_h);
    cudaGetSymbolAddress((void**)&y_l,  g_y_l);

    cudaFuncSetAttribute(moe_gemm<1, false, false>,
                         cudaFuncAttributeMaxDynamicSharedMemorySize, SMEM_TOTAL);
    cudaFuncSetAttribute(moe_gemm<1, true,  true>,
                         cudaFuncAttributeMaxDynamicSharedMemorySize, SMEM_TOTAL);
    cudaFuncSetAttribute(moe_gemm<0, false, true>,
                         cudaFuncAttributeMaxDynamicSharedMemorySize, SMEM_TOTAL);

    // ---- conversions ----
    // dmask [B][T][EC] -> dmT split [B][EC][T]
    tr_split<<<dim3(ECDIM / 32, TDIM / 32, BDIM), 256>>>(dmask, dmT_h, dmT_l,
                                                         TDIM, ECDIM);
    {
        long long n4 = (long long)BDIM * TDIM * ECDIM / 4;
        split_ew<<<(unsigned)((n4 + 255) / 256), 256>>>(comb, cmb_h, cmb_l, n4);
    }
    {
        long long n4 = (long long)BDIM * TDIM * DDIM / 4;
        split_ew<<<(unsigned)((n4 + 255) / 256), 256>>>(x, x_h, x_l, n4);
    }
    {
        long long n4 = (long long)EDIM * DDIM * HEDIM / 4;
        split_ew<<<(unsigned)((n4 + 255) / 256), 256>>>(w1, w1_h, w1_l, n4);
        split_ew<<<(unsigned)((n4 + 255) / 256), 256>>>(w2, w2_h, w2_l, n4);
    }

    // ---- K1: xd_b[EC,D] = dmT_b[EC,T] * x_b[T,D]  (split output) ----
    moe_gemm<1, false, false>
        <<<dim3(DDIM / BN, ECDIM / BM, BDIM), THREADS, SMEM_TOTAL>>>(
        dmT_h, dmT_l, x_h, x_l, nullptr, xd_h, xd_l, nullptr,
        TDIM, DDIM, DDIM, TDIM / BK,
        (long long)ECDIM * TDIM, (long long)TDIM * DDIM, (long long)ECDIM * DDIM,
        0, 0, 0);

    // ---- K2: h = gelu(xd * w1 + b1)  (split output) ----
    moe_gemm<1, true, true>
        <<<dim3(HEDIM / BN, CDIM / BM, BDIM * EDIM), THREADS, SMEM_TOTAL>>>(
        xd_h, xd_l, w1_h, w1_l, nullptr, h_h, h_l, b1,
        DDIM, HEDIM, HEDIM, DDIM / BK,
        (long long)CDIM * DDIM, (long long)DDIM * HEDIM, (long long)CDIM * HEDIM,
        EDIM, (long long)HEDIM, EDIM);

    // ---- K3: y = h * w2  (split output) ----
    moe_gemm<1, false, false>
        <<<dim3(ODIM / BN, CDIM / BM, BDIM * EDIM), THREADS, SMEM_TOTAL>>>(
        h_h, h_l, w2_h, w2_l, nullptr, y_h, y_l, nullptr,
        HEDIM, ODIM, ODIM, HEDIM / BK,
        (long long)CDIM * HEDIM, (long long)HEDIM * ODIM, (long long)CDIM * ODIM,
        EDIM, 0, 0);

    // ---- K4: out_b[T,O] = comb_b[T,EC] * y_b[EC,O] + b2  (fp32 output) ----
    moe_gemm<0, false, true>
        <<<dim3(ODIM / BN, TDIM / BM, BDIM), THREADS, SMEM_TOTAL>>>(
        cmb_h, cmb_l, y_h, y_l, out, nullptr, nullptr, b2,
        ECDIM, ODIM, ODIM, ECDIM / BK,
        (long long)TDIM * ECDIM, (long long)ECDIM * ODIM, (long long)TDIM * ODIM,
        0, 0, 1);
}

// round 5
// speedup vs baseline: 1.0630x; 1.0630x over previous
#include <cuda_runtime.h>
#include <cuda_bf16.h>
#include <math.h>
#include <stdint.h>

// ---------------- problem dims ----------------
#define BDIM 4
#define TDIM 2048
#define DDIM 512
#define EDIM 4
#define CDIM 1024
#define HEDIM 512
#define ODIM 512
#define ECDIM 4096

typedef __nv_bfloat16 bf16;

// ---------------- pre-split operand storage ----------------
__device__ bf16 g_dmT_h[(size_t)BDIM * ECDIM * TDIM];
__device__ bf16 g_dmT_l[(size_t)BDIM * ECDIM * TDIM];
__device__ bf16 g_cmb_h[(size_t)BDIM * TDIM * ECDIM];
__device__ bf16 g_cmb_l[(size_t)BDIM * TDIM * ECDIM];
__device__ bf16 g_x_h [(size_t)BDIM * TDIM * DDIM];
__device__ bf16 g_x_l [(size_t)BDIM * TDIM * DDIM];
__device__ bf16 g_w1_h[(size_t)EDIM * DDIM * HEDIM];
__device__ bf16 g_w1_l[(size_t)EDIM * DDIM * HEDIM];
__device__ bf16 g_w2_h[(size_t)EDIM * HEDIM * ODIM];
__device__ bf16 g_w2_l[(size_t)EDIM * HEDIM * ODIM];
__device__ bf16 g_xd_h[(size_t)BDIM * ECDIM * DDIM];
__device__ bf16 g_xd_l[(size_t)BDIM * ECDIM * DDIM];
__device__ bf16 g_h_h [(size_t)BDIM * ECDIM * HEDIM];
__device__ bf16 g_h_l [(size_t)BDIM * ECDIM * HEDIM];
__device__ bf16 g_y_h [(size_t)BDIM * ECDIM * ODIM];
__device__ bf16 g_y_l [(size_t)BDIM * ECDIM * ODIM];

// ---------------- split helpers ----------------
__device__ __forceinline__ void split4(const float4& v, uint2& h, uint2& l) {
    uint32_t ax = __float_as_uint(v.x), ay = __float_as_uint(v.y);
    uint32_t az = __float_as_uint(v.z), aw = __float_as_uint(v.w);
    h.x = (ax >> 16) | (ay & 0xffff0000u);
    h.y = (az >> 16) | (aw & 0xffff0000u);
    float lx = v.x - __uint_as_float(ax & 0xffff0000u);
    float ly = v.y - __uint_as_float(ay & 0xffff0000u);
    float lz = v.z - __uint_as_float(az & 0xffff0000u);
    float lw = v.w - __uint_as_float(aw & 0xffff0000u);
    __nv_bfloat162 p0 = __floats2bfloat162_rn(lx, ly);
    __nv_bfloat162 p1 = __floats2bfloat162_rn(lz, lw);
    l.x = *reinterpret_cast<uint32_t*>(&p0);
    l.y = *reinterpret_cast<uint32_t*>(&p1);
}
__device__ __forceinline__ uint32_t pack_hi2(float a, float b) {
    return (__float_as_uint(a) >> 16) | (__float_as_uint(b) & 0xffff0000u);
}
__device__ __forceinline__ uint32_t pack_lo2(float a, float b) {
    float ra = a - __uint_as_float(__float_as_uint(a) & 0xffff0000u);
    float rb = b - __uint_as_float(__float_as_uint(b) & 0xffff0000u);
    __nv_bfloat162 p = __floats2bfloat162_rn(ra, rb);
    return *reinterpret_cast<uint32_t*>(&p);
}

// ---------------- conversion kernels ----------------
__global__ void split_ew(const float* __restrict__ s, bf16* __restrict__ hi,
                         bf16* __restrict__ lo, long long n4) {
    long long i = (long long)blockIdx.x * blockDim.x + threadIdx.x;
    if (i < n4) {
        float4 v = reinterpret_cast<const float4*>(s)[i];
        uint2 h, l; split4(v, h, l);
        reinterpret_cast<uint2*>(hi)[i] = h;
        reinterpret_cast<uint2*>(lo)[i] = l;
    }
}
// src [R][Cc] per batch -> dst [Cc][R] split, vectorized u32 stores
// block handles 64 rows (t) x 32 cols (ec)
__global__ void tr_split(const float* __restrict__ s, bf16* __restrict__ hi,
                         bf16* __restrict__ lo, int R, int Cc) {
    __shared__ float t[64][33];
    const int c0 = blockIdx.x * 32, r0 = blockIdx.y * 64;
    const size_t zoff = (size_t)blockIdx.z * R * Cc;
    const float* S = s + zoff;
    const int tx = threadIdx.x & 31, ty = threadIdx.x >> 5;
#pragma unroll
    for (int i = 0; i < 8; i++) {
        int r = ty + i * 8;
        t[r][tx] = S[(size_t)(r0 + r) * Cc + c0 + tx];
    }
    __syncthreads();
    const int rr = threadIdx.x >> 3, pair = threadIdx.x & 7;
#pragma unroll
    for (int i = 0; i < 4; i++) {
        int tcol = (pair + i * 8) * 2;
        float a = t[tcol][rr], b = t[tcol + 1][rr];
        size_t o = zoff + (size_t)(c0 + rr) * R + r0 + tcol;
        *reinterpret_cast<uint32_t*>(hi + o) = pack_hi2(a, b);
        *reinterpret_cast<uint32_t*>(lo + o) = pack_lo2(a, b);
    }
}

// ---------------- GEMM tile config ----------------
constexpr int BM = 128, BN = 256, BK = 32;
constexpr int THREADS = 256;
constexpr int OFF_AHI = 0;
constexpr int OFF_ALO = 8192;
constexpr int OFF_BHI = 16384;
constexpr int OFF_BLO = 32768;
constexpr int STAGE   = 49152;
constexpr int STAGES  = 3;
constexpr int SMEM_TOTAL = STAGES * STAGE;   // 144 KB

__device__ __forceinline__ int a_off(int m, int kc) {   // kc 0..3, rows 64B
    return m * 64 + ((kc ^ ((m >> 1) & 3)) << 4);
}
__device__ __forceinline__ int b_off(int k, int nc) {   // nc 0..31, rows 512B
    return k * 512 + ((nc ^ (k & 7)) << 4);
}
__device__ __forceinline__ uint32_t smem_u32(const void* p) {
    uint32_t a;
    asm("{ .reg .u64 t; cvta.to.shared.u64 t, %1; cvt.u32.u64 %0, t; }"
        : "=r"(a) : "l"(p));
    return a;
}
__device__ __forceinline__ void ldsm4(uint32_t* r, uint32_t addr) {
    asm volatile("ldmatrix.sync.aligned.m8n8.x4.shared.b16 {%0,%1,%2,%3}, [%4];"
                 : "=r"(r[0]), "=r"(r[1]), "=r"(r[2]), "=r"(r[3]) : "r"(addr));
}
__device__ __forceinline__ void ldsm4t(uint32_t* r, uint32_t addr) {
    asm volatile("ldmatrix.sync.aligned.m8n8.x4.trans.shared.b16 {%0,%1,%2,%3}, [%4];"
                 : "=r"(r[0]), "=r"(r[1]), "=r"(r[2]), "=r"(r[3]) : "r"(addr));
}
__device__ __forceinline__ void mma_bf16(float* d, const uint32_t* a, const uint32_t* b) {
    asm volatile(
        "mma.sync.aligned.m16n8k16.row.col.f32.bf16.bf16.f32 "
        "{%0,%1,%2,%3}, {%4,%5,%6,%7}, {%8,%9}, {%0,%1,%2,%3};"
        : "+f"(d[0]), "+f"(d[1]), "+f"(d[2]), "+f"(d[3])
        : "r"(a[0]), "r"(a[1]), "r"(a[2]), "r"(a[3]), "r"(b[0]), "r"(b[1]));
}
__device__ __forceinline__ void cp16(uint32_t dst, const void* src) {
    asm volatile("cp.async.cg.shared.global [%0], [%1], 16;" :: "r"(dst), "l"(src));
}
__device__ __forceinline__ void cp_commit() {
    asm volatile("cp.async.commit_group;" ::: "memory");
}
__device__ __forceinline__ void cp_wait1() {
    asm volatile("cp.async.wait_group 1;" ::: "memory");
}

// ---------------- main GEMM kernel ----------------
// CTA 128x256, warp tile 64x64 (2x4 warps). Pre-split bf16 hi/lo operands.
template<int OUTM, bool GELU_, bool BIAS_>
__global__ __launch_bounds__(THREADS, 1)
void moe_gemm(const bf16* __restrict__ Ah, const bf16* __restrict__ Al,
              const bf16* __restrict__ Bh, const bf16* __restrict__ Bl,
              float* __restrict__ Cf, bf16* __restrict__ Ch, bf16* __restrict__ Cl,
              const float* __restrict__ biasBase,
              int lda, int ldb, int ldc, int KT,
              long long sA, long long sB, long long sC, int bMod,
              long long sBias, int biasMod)
{
    extern __shared__ char smem[];
    const int tid  = threadIdx.x;
    const int lane = tid & 31;
    const int wid  = tid >> 5;
    const int wm   = (wid & 1) * 64;
    const int wn   = (wid >> 1) * 64;

    const int z = blockIdx.z;
    const long long aoff = (long long)z * sA;
    const long long boff = (long long)(bMod ? (z % bMod) : z) * sB;
    const long long coff = (long long)z * sC;
    const float* bias = BIAS_
        ? biasBase + (long long)(biasMod ? (z % biasMod) : z) * sBias : nullptr;

    const int m0 = blockIdx.y * BM;
    const int n0 = blockIdx.x * BN;
    const uint32_t sbase = smem_u32(smem);

    const bf16* pAh = Ah + aoff; const bf16* pAl = Al + aoff;
    const bf16* pBh = Bh + boff; const bf16* pBl = Bl + boff;

    float acc[4][8][4];
#pragma unroll
    for (int i = 0; i < 4; i++)
#pragma unroll
        for (int j = 0; j < 8; j++)
#pragma unroll
            for (int c = 0; c < 4; c++) acc[i][j][c] = 0.f;

    auto issue = [&](int it) {
        if (it < KT) {
            const uint32_t st = sbase + (it % STAGES) * STAGE;
            const int k0 = it * BK;
#pragma unroll
            for (int i = 0; i < 2; i++) {
                int c = tid + i * THREADS;
                int m = c >> 2, kc = c & 3;
                size_t g = (size_t)(m0 + m) * lda + k0 + kc * 8;
                int off = a_off(m, kc);
                cp16(st + OFF_AHI + off, pAh + g);
                cp16(st + OFF_ALO + off, pAl + g);
            }
#pragma unroll
            for (int i = 0; i < 4; i++) {
                int c = tid + i * THREADS;
                int k = c >> 5, nc = c & 31;
                size_t g = (size_t)(k0 + k) * ldb + n0 + nc * 8;
                int off = b_off(k, nc);
                cp16(st + OFF_BHI + off, pBh + g);
                cp16(st + OFF_BLO + off, pBl + g);
            }
        }
        cp_commit();
    };

    issue(0); issue(1);

    for (int it = 0; it < KT; ++it) {
        cp_wait1();
        __syncthreads();
        issue(it + 2);

        const uint32_t cur = sbase + (it % STAGES) * STAGE;
#pragma unroll
        for (int kh = 0; kh < 2; kh++) {
            uint32_t ahr[4][4], alr[4][4];
#pragma unroll
            for (int mf = 0; mf < 4; mf++) {
                int row = wm + mf * 16 + (lane & 15);
                int chunk = kh * 2 + (lane >> 4);
                int off = a_off(row, chunk);
                ldsm4(ahr[mf], cur + OFF_AHI + off);
                ldsm4(alr[mf], cur + OFF_ALO + off);
            }
            uint32_t bhr[4][4], blr[4][4];
#pragma unroll
            for (int nb = 0; nb < 4; nb++) {
                int k = kh * 16 + ((lane >> 3) & 1) * 8 + (lane & 7);
                int nchunk = ((wn + nb * 16) >> 3) + (lane >> 4);
                int off = b_off(k, nchunk);
                ldsm4t(bhr[nb], cur + OFF_BHI + off);
                ldsm4t(blr[nb], cur + OFF_BLO + off);
            }
#pragma unroll
            for (int mf = 0; mf < 4; mf++)
#pragma unroll
                for (int nf = 0; nf < 8; nf++) {
                    const uint32_t* bhf = &bhr[nf >> 1][(nf & 1) * 2];
                    const uint32_t* blf = &blr[nf >> 1][(nf & 1) * 2];
                    mma_bf16(acc[mf][nf], ahr[mf], bhf);
                    mma_bf16(acc[mf][nf], ahr[mf], blf);
                    mma_bf16(acc[mf][nf], alr[mf], bhf);
                }
        }
    }

    // ---- epilogue ----
    const int g = lane >> 2, t = lane & 3;
#pragma unroll
    for (int mf = 0; mf < 4; mf++) {
#pragma unroll
        for (int nf = 0; nf < 8; nf++) {
            int row = m0 + wm + mf * 16 + g;
            int col = n0 + wn + nf * 8 + t * 2;
            float v0 = acc[mf][nf][0], v1 = acc[mf][nf][1];
            float v2 = acc[mf][nf][2], v3 = acc[mf][nf][3];
            if (BIAS_) {
                float2 bv = *reinterpret_cast<const float2*>(bias + col);
                v0 += bv.x; v1 += bv.y; v2 += bv.x; v3 += bv.y;
            }
            if (GELU_) {
                v0 = 0.5f * v0 * (1.0f + erff(v0 * 0.70710678118654752f));
                v1 = 0.5f * v1 * (1.0f + erff(v1 * 0.70710678118654752f));
                v2 = 0.5f * v2 * (1.0f + erff(v2 * 0.70710678118654752f));
                v3 = 0.5f * v3 * (1.0f + erff(v3 * 0.70710678118654752f));
            }
            if (OUTM == 0) {
                *reinterpret_cast<float2*>(Cf + coff + (size_t)row * ldc + col) =
                    make_float2(v0, v1);
                *reinterpret_cast<float2*>(Cf + coff + (size_t)(row + 8) * ldc + col) =
                    make_float2(v2, v3);
            } else {
                size_t o0 = (size_t)(coff + (size_t)row * ldc + col);
                size_t o1 = (size_t)(coff + (size_t)(row + 8) * ldc + col);
                *reinterpret_cast<uint32_t*>(Ch + o0) = pack_hi2(v0, v1);
                *reinterpret_cast<uint32_t*>(Cl + o0) = pack_lo2(v0, v1);
                *reinterpret_cast<uint32_t*>(Ch + o1) = pack_hi2(v2, v3);
                *reinterpret_cast<uint32_t*>(Cl + o1) = pack_lo2(v2, v3);
            }
        }
    }
}

// ---------------- launcher ----------------
extern "C" void kernel_launch(void* const* d_in, const int* in_sizes, int n_in,
                              void* d_out, int out_size)
{
    const float* x     = (const float*)d_in[0];
    const float* dmask = (const float*)d_in[1];
    const float* comb  = (const float*)d_in[2];
    const float* w1    = (const float*)d_in[3];
    const float* b1    = (const float*)d_in[4];
    const float* w2    = (const float*)d_in[5];
    const float* b2    = (const float*)d_in[6];
    float* out = (float*)d_out;

    bf16 *dmT_h, *dmT_l, *cmb_h, *cmb_l, *x_h, *x_l, *w1_h, *w1_l, *w2_h, *w2_l;
    bf16 *xd_h, *xd_l, *h_h, *h_l, *y_h, *y_l;
    cudaGetSymbolAddress((void**)&dmT_h, g_dmT_h);
    cudaGetSymbolAddress((void**)&dmT_l, g_dmT_l);
    cudaGetSymbolAddress((void**)&cmb_h, g_cmb_h);
    cudaGetSymbolAddress((void**)&cmb_l, g_cmb_l);
    cudaGetSymbolAddress((void**)&x_h,  g_x_h);
    cudaGetSymbolAddress((void**)&x_l,  g_x_l);
    cudaGetSymbolAddress((void**)&w1_h, g_w1_h);
    cudaGetSymbolAddress((void**)&w1_l, g_w1_l);
    cudaGetSymbolAddress((void**)&w2_h, g_w2_h);
    cudaGetSymbolAddress((void**)&w2_l, g_w2_l);
    cudaGetSymbolAddress((void**)&xd_h, g_xd_h);
    cudaGetSymbolAddress((void**)&xd_l, g_xd_l);
    cudaGetSymbolAddress((void**)&h_h,  g_h_h);
    cudaGetSymbolAddress((void**)&h_l,  g_h_l);
    cudaGetSymbolAddress((void**)&y_h,  g_y_h);
    cudaGetSymbolAddress((void**)&y_l,  g_y_l);

    cudaFuncSetAttribute(moe_gemm<1, false, false>,
                         cudaFuncAttributeMaxDynamicSharedMemorySize, SMEM_TOTAL);
    cudaFuncSetAttribute(moe_gemm<1, true,  true>,
                         cudaFuncAttributeMaxDynamicSharedMemorySize, SMEM_TOTAL);
    cudaFuncSetAttribute(moe_gemm<0, false, true>,
                         cudaFuncAttributeMaxDynamicSharedMemorySize, SMEM_TOTAL);

    // ---- conversions ----
    tr_split<<<dim3(ECDIM / 32, TDIM / 64, BDIM), 256>>>(dmask, dmT_h, dmT_l,
                                                         TDIM, ECDIM);
    {
        long long n4 = (long long)BDIM * TDIM * ECDIM / 4;
        split_ew<<<(unsigned)((n4 + 255) / 256), 256>>>(comb, cmb_h, cmb_l, n4);
    }
    {
        long long n4 = (long long)BDIM * TDIM * DDIM / 4;
        split_ew<<<(unsigned)((n4 + 255) / 256), 256>>>(x, x_h, x_l, n4);
    }
    {
        long long n4 = (long long)EDIM * DDIM * HEDIM / 4;
        split_ew<<<(unsigned)((n4 + 255) / 256), 256>>>(w1, w1_h, w1_l, n4);
        split_ew<<<(unsigned)((n4 + 255) / 256), 256>>>(w2, w2_h, w2_l, n4);
    }

    // ---- K1: xd_b[EC,D] = dmT_b[EC,T] * x_b[T,D] ----
    moe_gemm<1, false, false>
        <<<dim3(DDIM / BN, ECDIM / BM, BDIM), THREADS, SMEM_TOTAL>>>(
        dmT_h, dmT_l, x_h, x_l, nullptr, xd_h, xd_l, nullptr,
        TDIM, DDIM, DDIM, TDIM / BK,
        (long long)ECDIM * TDIM, (long long)TDIM * DDIM, (long long)ECDIM * DDIM,
        0, 0, 0);

    // ---- K2: h = gelu(xd * w1 + b1) ----
    moe_gemm<1, true, true>
        <<<dim3(HEDIM / BN, CDIM / BM, BDIM * EDIM), THREADS, SMEM_TOTAL>>>(
        xd_h, xd_l, w1_h, w1_l, nullptr, h_h, h_l, b1,
        DDIM, HEDIM, HEDIM, DDIM / BK,
        (long long)CDIM * DDIM, (long long)DDIM * HEDIM, (long long)CDIM * HEDIM,
        EDIM, (long long)HEDIM, EDIM);

    // ---- K3: y = h * w2 ----
    moe_gemm<1, false, false>
        <<<dim3(ODIM / BN, CDIM / BM, BDIM * EDIM), THREADS, SMEM_TOTAL>>>(
        h_h, h_l, w2_h, w2_l, nullptr, y_h, y_l, nullptr,
        HEDIM, ODIM, ODIM, HEDIM / BK,
        (long long)CDIM * HEDIM, (long long)HEDIM * ODIM, (long long)CDIM * ODIM,
        EDIM, 0, 0);

    // ---- K4: out_b[T,O] = comb_b[T,EC] * y_b[EC,O] + b2 ----
    moe_gemm<0, false, true>
        <<<dim3(ODIM / BN, TDIM / BM, BDIM), THREADS, SMEM_TOTAL>>>(
        cmb_h, cmb_l, y_h, y_l, out, nullptr, nullptr, b2,
        ECDIM, ODIM, ODIM, ECDIM / BK,
        (long long)TDIM * ECDIM, (long long)ECDIM * ODIM, (long long)TDIM * ODIM,
        0, 0, 1);
}

// round 6
// speedup vs baseline: 1.3378x; 1.2585x over previous
#include <cuda_runtime.h>
#include <cuda_fp16.h>
#include <math.h>
#include <stdint.h>

// ---------------- problem dims ----------------
#define BDIM 4
#define TDIM 2048
#define DDIM 512
#define EDIM 4
#define CDIM 1024
#define HEDIM 512
#define ODIM 512
#define ECDIM 4096

typedef __half f16;

// ---------------- operand storage (no cudaMalloc allowed) ----------------
__device__ f16 g_dmT_h[(size_t)BDIM * ECDIM * TDIM];
__device__ f16 g_dmT_l[(size_t)BDIM * ECDIM * TDIM];
__device__ f16 g_cmb_h[(size_t)BDIM * TDIM * ECDIM];
__device__ f16 g_cmb_l[(size_t)BDIM * TDIM * ECDIM];
__device__ f16 g_x_s [(size_t)BDIM * TDIM * DDIM];      // single fp16
__device__ f16 g_w1_h[(size_t)EDIM * DDIM * HEDIM];
__device__ f16 g_w1_l[(size_t)EDIM * DDIM * HEDIM];
__device__ f16 g_w2_h[(size_t)EDIM * HEDIM * ODIM];
__device__ f16 g_w2_l[(size_t)EDIM * HEDIM * ODIM];
__device__ f16 g_xd_h[(size_t)BDIM * ECDIM * DDIM];
__device__ f16 g_xd_l[(size_t)BDIM * ECDIM * DDIM];
__device__ f16 g_h_h [(size_t)BDIM * ECDIM * HEDIM];
__device__ f16 g_h_l [(size_t)BDIM * ECDIM * HEDIM];
__device__ f16 g_y_s [(size_t)BDIM * ECDIM * ODIM];     // single fp16

// ---------------- split helpers (fp16 rn split) ----------------
__device__ __forceinline__ uint32_t pack_h2(float a, float b) {
    __half2 p = __floats2half2_rn(a, b);
    return *reinterpret_cast<uint32_t*>(&p);
}
__device__ __forceinline__ uint32_t pack_l2(float a, float b) {
    float ra = a - __half2float(__float2half_rn(a));
    float rb = b - __half2float(__float2half_rn(b));
    __half2 p = __floats2half2_rn(ra, rb);
    return *reinterpret_cast<uint32_t*>(&p);
}
__device__ __forceinline__ void split4(const float4& v, uint2& h, uint2& l) {
    h.x = pack_h2(v.x, v.y); h.y = pack_h2(v.z, v.w);
    l.x = pack_l2(v.x, v.y); l.y = pack_l2(v.z, v.w);
}

// ---------------- conversion kernels ----------------
__global__ void split_ew(const float* __restrict__ s, f16* __restrict__ hi,
                         f16* __restrict__ lo, long long n4) {
    long long i = (long long)blockIdx.x * blockDim.x + threadIdx.x;
    if (i < n4) {
        float4 v = reinterpret_cast<const float4*>(s)[i];
        uint2 h, l; split4(v, h, l);
        reinterpret_cast<uint2*>(hi)[i] = h;
        reinterpret_cast<uint2*>(lo)[i] = l;
    }
}
__global__ void conv_ew(const float* __restrict__ s, f16* __restrict__ d,
                        long long n4) {
    long long i = (long long)blockIdx.x * blockDim.x + threadIdx.x;
    if (i < n4) {
        float4 v = reinterpret_cast<const float4*>(s)[i];
        uint2 h;
        h.x = pack_h2(v.x, v.y); h.y = pack_h2(v.z, v.w);
        reinterpret_cast<uint2*>(d)[i] = h;
    }
}
// src [R][Cc] per batch -> dst [Cc][R] split
__global__ void tr_split(const float* __restrict__ s, f16* __restrict__ hi,
                         f16* __restrict__ lo, int R, int Cc) {
    __shared__ float t[64][33];
    const int c0 = blockIdx.x * 32, r0 = blockIdx.y * 64;
    const size_t zoff = (size_t)blockIdx.z * R * Cc;
    const float* S = s + zoff;
    const int tx = threadIdx.x & 31, ty = threadIdx.x >> 5;
#pragma unroll
    for (int i = 0; i < 8; i++) {
        int r = ty + i * 8;
        t[r][tx] = S[(size_t)(r0 + r) * Cc + c0 + tx];
    }
    __syncthreads();
    const int rr = threadIdx.x >> 3, pair = threadIdx.x & 7;
#pragma unroll
    for (int i = 0; i < 4; i++) {
        int tcol = (pair + i * 8) * 2;
        float a = t[tcol][rr], b = t[tcol + 1][rr];
        size_t o = zoff + (size_t)(c0 + rr) * R + r0 + tcol;
        *reinterpret_cast<uint32_t*>(hi + o) = pack_h2(a, b);
        *reinterpret_cast<uint32_t*>(lo + o) = pack_l2(a, b);
    }
}

// ---------------- GEMM tile config ----------------
constexpr int BM = 128, BN = 256, BK = 32;
constexpr int THREADS = 256;

__device__ __forceinline__ int a_off(int m, int kc) {   // rows 64B
    return m * 64 + ((kc ^ ((m >> 1) & 3)) << 4);
}
__device__ __forceinline__ int b_off(int k, int nc) {   // rows 512B
    return k * 512 + ((nc ^ (k & 7)) << 4);
}
__device__ __forceinline__ uint32_t smem_u32(const void* p) {
    uint32_t a;
    asm("{ .reg .u64 t; cvta.to.shared.u64 t, %1; cvt.u32.u64 %0, t; }"
        : "=r"(a) : "l"(p));
    return a;
}
__device__ __forceinline__ void ldsm4(uint32_t* r, uint32_t addr) {
    asm volatile("ldmatrix.sync.aligned.m8n8.x4.shared.b16 {%0,%1,%2,%3}, [%4];"
                 : "=r"(r[0]), "=r"(r[1]), "=r"(r[2]), "=r"(r[3]) : "r"(addr));
}
__device__ __forceinline__ void ldsm4t(uint32_t* r, uint32_t addr) {
    asm volatile("ldmatrix.sync.aligned.m8n8.x4.trans.shared.b16 {%0,%1,%2,%3}, [%4];"
                 : "=r"(r[0]), "=r"(r[1]), "=r"(r[2]), "=r"(r[3]) : "r"(addr));
}
__device__ __forceinline__ void mma_f16(float* d, const uint32_t* a, const uint32_t* b) {
    asm volatile(
        "mma.sync.aligned.m16n8k16.row.col.f32.f16.f16.f32 "
        "{%0,%1,%2,%3}, {%4,%5,%6,%7}, {%8,%9}, {%0,%1,%2,%3};"
        : "+f"(d[0]), "+f"(d[1]), "+f"(d[2]), "+f"(d[3])
        : "r"(a[0]), "r"(a[1]), "r"(a[2]), "r"(a[3]), "r"(b[0]), "r"(b[1]));
}
__device__ __forceinline__ void cp16(uint32_t dst, const void* src) {
    asm volatile("cp.async.cg.shared.global [%0], [%1], 16;" :: "r"(dst), "l"(src));
}
__device__ __forceinline__ void cp_commit() {
    asm volatile("cp.async.commit_group;" ::: "memory");
}
template<int N>
__device__ __forceinline__ void cp_wait() {
    asm volatile("cp.async.wait_group %0;" :: "n"(N) : "memory");
}

// ---------------- main GEMM kernel ----------------
// CTA 128x256, warp tile 64x64. fp16 split operands.
// PASSES: 2 = A split x B single; 3 = A split x B split (AhBh+AhBl+AlBh)
// OUTM: 0 = fp32, 1 = split f16 pair, 2 = single f16
template<int PASSES, int OUTM, bool GELU_, bool BIAS_>
__global__ __launch_bounds__(THREADS, 1)
void moe_gemm(const f16* __restrict__ Ah, const f16* __restrict__ Al,
              const f16* __restrict__ Bh, const f16* __restrict__ Bl,
              float* __restrict__ Cf, f16* __restrict__ Ch, f16* __restrict__ Cl,
              const float* __restrict__ biasBase,
              int lda, int ldb, int ldc, int KT,
              long long sA, long long sB, long long sC, int bMod,
              long long sBias, int biasMod)
{
    constexpr int OFF_ALO = 8192;
    constexpr int OFF_BHI = 16384;
    constexpr int OFF_BLO = 32768;                        // P3 only
    constexpr int STAGE   = (PASSES == 2) ? 32768 : 49152;
    constexpr int NSTG    = (PASSES == 2) ? 4 : 3;

    extern __shared__ char smem[];
    const int tid  = threadIdx.x;
    const int lane = tid & 31;
    const int wid  = tid >> 5;
    const int wm   = (wid & 1) * 64;
    const int wn   = (wid >> 1) * 64;

    const int z = blockIdx.z;
    const long long aoff = (long long)z * sA;
    const long long boff = (long long)(bMod ? (z % bMod) : z) * sB;
    const long long coff = (long long)z * sC;
    const float* bias = BIAS_
        ? biasBase + (long long)(biasMod ? (z % biasMod) : z) * sBias : nullptr;

    const int m0 = blockIdx.y * BM;
    const int n0 = blockIdx.x * BN;
    const uint32_t sbase = smem_u32(smem);

    const f16* pAh = Ah + aoff; const f16* pAl = Al + aoff;
    const f16* pBh = Bh + boff;
    const f16* pBl = (PASSES == 3) ? Bl + boff : nullptr;

    float acc[4][8][4];
#pragma unroll
    for (int i = 0; i < 4; i++)
#pragma unroll
        for (int j = 0; j < 8; j++)
#pragma unroll
            for (int c = 0; c < 4; c++) acc[i][j][c] = 0.f;

    auto issue = [&](int it) {
        if (it < KT) {
            const uint32_t st = sbase + (it % NSTG) * STAGE;
            const int k0 = it * BK;
#pragma unroll
            for (int i = 0; i < 2; i++) {
                int c = tid + i * THREADS;
                int m = c >> 2, kc = c & 3;
                size_t g = (size_t)(m0 + m) * lda + k0 + kc * 8;
                int off = a_off(m, kc);
                cp16(st + off, pAh + g);
                cp16(st + OFF_ALO + off, pAl + g);
            }
#pragma unroll
            for (int i = 0; i < 4; i++) {
                int c = tid + i * THREADS;
                int k = c >> 5, nc = c & 31;
                size_t g = (size_t)(k0 + k) * ldb + n0 + nc * 8;
                int off = b_off(k, nc);
                cp16(st + OFF_BHI + off, pBh + g);
                if (PASSES == 3) cp16(st + OFF_BLO + off, pBl + g);
            }
        }
        cp_commit();
    };

    issue(0); issue(1);
    if (PASSES == 2) issue(2);

    for (int it = 0; it < KT; ++it) {
        if (PASSES == 2) cp_wait<2>(); else cp_wait<1>();
        __syncthreads();
        issue(it + NSTG - 1);

        const uint32_t cur = sbase + (it % NSTG) * STAGE;
#pragma unroll
        for (int kh = 0; kh < 2; kh++) {
            uint32_t ahr[4][4], alr[4][4];
#pragma unroll
            for (int mf = 0; mf < 4; mf++) {
                int row = wm + mf * 16 + (lane & 15);
                int chunk = kh * 2 + (lane >> 4);
                int off = a_off(row, chunk);
                ldsm4(ahr[mf], cur + off);
                ldsm4(alr[mf], cur + OFF_ALO + off);
            }
            uint32_t bhr[4][4];
            uint32_t blr[4][4];
#pragma unroll
            for (int nb = 0; nb < 4; nb++) {
                int k = kh * 16 + ((lane >> 3) & 1) * 8 + (lane & 7);
                int nchunk = ((wn + nb * 16) >> 3) + (lane >> 4);
                int off = b_off(k, nchunk);
                ldsm4t(bhr[nb], cur + OFF_BHI + off);
                if (PASSES == 3) ldsm4t(blr[nb], cur + OFF_BLO + off);
            }
#pragma unroll
            for (int mf = 0; mf < 4; mf++)
#pragma unroll
                for (int nf = 0; nf < 8; nf++) {
                    const uint32_t* bhf = &bhr[nf >> 1][(nf & 1) * 2];
                    mma_f16(acc[mf][nf], ahr[mf], bhf);
                    mma_f16(acc[mf][nf], alr[mf], bhf);
                    if (PASSES == 3) {
                        const uint32_t* blf = &blr[nf >> 1][(nf & 1) * 2];
                        mma_f16(acc[mf][nf], ahr[mf], blf);
                    }
                }
        }
    }

    // ---- epilogue ----
    const int g = lane >> 2, t = lane & 3;
#pragma unroll
    for (int mf = 0; mf < 4; mf++) {
#pragma unroll
        for (int nf = 0; nf < 8; nf++) {
            int row = m0 + wm + mf * 16 + g;
            int col = n0 + wn + nf * 8 + t * 2;
            float v0 = acc[mf][nf][0], v1 = acc[mf][nf][1];
            float v2 = acc[mf][nf][2], v3 = acc[mf][nf][3];
            if (BIAS_) {
                float2 bv = *reinterpret_cast<const float2*>(bias + col);
                v0 += bv.x; v1 += bv.y; v2 += bv.x; v3 += bv.y;
            }
            if (GELU_) {
                v0 = 0.5f * v0 * (1.0f + erff(v0 * 0.70710678118654752f));
                v1 = 0.5f * v1 * (1.0f + erff(v1 * 0.70710678118654752f));
                v2 = 0.5f * v2 * (1.0f + erff(v2 * 0.70710678118654752f));
                v3 = 0.5f * v3 * (1.0f + erff(v3 * 0.70710678118654752f));
            }
            size_t o0 = (size_t)(coff + (size_t)row * ldc + col);
            size_t o1 = (size_t)(coff + (size_t)(row + 8) * ldc + col);
            if (OUTM == 0) {
                *reinterpret_cast<float2*>(Cf + o0) = make_float2(v0, v1);
                *reinterpret_cast<float2*>(Cf + o1) = make_float2(v2, v3);
            } else if (OUTM == 1) {
                *reinterpret_cast<uint32_t*>(Ch + o0) = pack_h2(v0, v1);
                *reinterpret_cast<uint32_t*>(Cl + o0) = pack_l2(v0, v1);
                *reinterpret_cast<uint32_t*>(Ch + o1) = pack_h2(v2, v3);
                *reinterpret_cast<uint32_t*>(Cl + o1) = pack_l2(v2, v3);
            } else {
                *reinterpret_cast<uint32_t*>(Ch + o0) = pack_h2(v0, v1);
                *reinterpret_cast<uint32_t*>(Ch + o1) = pack_h2(v2, v3);
            }
        }
    }
}

// ---------------- launcher ----------------
extern "C" void kernel_launch(void* const* d_in, const int* in_sizes, int n_in,
                              void* d_out, int out_size)
{
    const float* x     = (const float*)d_in[0];
    const float* dmask = (const float*)d_in[1];
    const float* comb  = (const float*)d_in[2];
    const float* w1    = (const float*)d_in[3];
    const float* b1    = (const float*)d_in[4];
    const float* w2    = (const float*)d_in[5];
    const float* b2    = (const float*)d_in[6];
    float* out = (float*)d_out;

    f16 *dmT_h, *dmT_l, *cmb_h, *cmb_l, *x_s, *w1_h, *w1_l, *w2_h, *w2_l;
    f16 *xd_h, *xd_l, *h_h, *h_l, *y_s;
    cudaGetSymbolAddress((void**)&dmT_h, g_dmT_h);
    cudaGetSymbolAddress((void**)&dmT_l, g_dmT_l);
    cudaGetSymbolAddress((void**)&cmb_h, g_cmb_h);
    cudaGetSymbolAddress((void**)&cmb_l, g_cmb_l);
    cudaGetSymbolAddress((void**)&x_s,  g_x_s);
    cudaGetSymbolAddress((void**)&w1_h, g_w1_h);
    cudaGetSymbolAddress((void**)&w1_l, g_w1_l);
    cudaGetSymbolAddress((void**)&w2_h, g_w2_h);
    cudaGetSymbolAddress((void**)&w2_l, g_w2_l);
    cudaGetSymbolAddress((void**)&xd_h, g_xd_h);
    cudaGetSymbolAddress((void**)&xd_l, g_xd_l);
    cudaGetSymbolAddress((void**)&h_h,  g_h_h);
    cudaGetSymbolAddress((void**)&h_l,  g_h_l);
    cudaGetSymbolAddress((void**)&y_s,  g_y_s);

    constexpr int SM2 = 4 * 32768;   // 2-pass: 4 stages x 32KB
    constexpr int SM3 = 3 * 49152;   // 3-pass: 3 stages x 48KB
    cudaFuncSetAttribute(moe_gemm<2, 1, false, false>,
                         cudaFuncAttributeMaxDynamicSharedMemorySize, SM2);
    cudaFuncSetAttribute(moe_gemm<3, 1, true,  true>,
                         cudaFuncAttributeMaxDynamicSharedMemorySize, SM3);
    cudaFuncSetAttribute(moe_gemm<3, 2, false, false>,
                         cudaFuncAttributeMaxDynamicSharedMemorySize, SM3);
    cudaFuncSetAttribute(moe_gemm<2, 0, false, true>,
                         cudaFuncAttributeMaxDynamicSharedMemorySize, SM2);

    // ---- conversions ----
    tr_split<<<dim3(ECDIM / 32, TDIM / 64, BDIM), 256>>>(dmask, dmT_h, dmT_l,
                                                         TDIM, ECDIM);
    {
        long long n4 = (long long)BDIM * TDIM * ECDIM / 4;
        split_ew<<<(unsigned)((n4 + 255) / 256), 256>>>(comb, cmb_h, cmb_l, n4);
    }
    {
        long long n4 = (long long)BDIM * TDIM * DDIM / 4;
        conv_ew<<<(unsigned)((n4 + 255) / 256), 256>>>(x, x_s, n4);
    }
    {
        long long n4 = (long long)EDIM * DDIM * HEDIM / 4;
        split_ew<<<(unsigned)((n4 + 255) / 256), 256>>>(w1, w1_h, w1_l, n4);
        split_ew<<<(unsigned)((n4 + 255) / 256), 256>>>(w2, w2_h, w2_l, n4);
    }

    // ---- K1 (2-pass): xd_b[EC,D] = dmT_b[EC,T] * x_b[T,D], split output ----
    moe_gemm<2, 1, false, false>
        <<<dim3(DDIM / BN, ECDIM / BM, BDIM), THREADS, SM2>>>(
        dmT_h, dmT_l, x_s, nullptr, nullptr, xd_h, xd_l, nullptr,
        TDIM, DDIM, DDIM, TDIM / BK,
        (long long)ECDIM * TDIM, (long long)TDIM * DDIM, (long long)ECDIM * DDIM,
        0, 0, 0);

    // ---- K2 (3-pass): h = gelu(xd * w1 + b1), split output ----
    moe_gemm<3, 1, true, true>
        <<<dim3(HEDIM / BN, CDIM / BM, BDIM * EDIM), THREADS, SM3>>>(
        xd_h, xd_l, w1_h, w1_l, nullptr, h_h, h_l, b1,
        DDIM, HEDIM, HEDIM, DDIM / BK,
        (long long)CDIM * DDIM, (long long)DDIM * HEDIM, (long long)CDIM * HEDIM,
        EDIM, (long long)HEDIM, EDIM);

    // ---- K3 (3-pass): y = h * w2, single f16 output ----
    moe_gemm<3, 2, false, false>
        <<<dim3(ODIM / BN, CDIM / BM, BDIM * EDIM), THREADS, SM3>>>(
        h_h, h_l, w2_h, w2_l, nullptr, y_s, nullptr, nullptr,
        HEDIM, ODIM, ODIM, HEDIM / BK,
        (long long)CDIM * HEDIM, (long long)HEDIM * ODIM, (long long)CDIM * ODIM,
        EDIM, 0, 0);

    // ---- K4 (2-pass): out_b[T,O] = comb_b[T,EC] * y_b[EC,O] + b2, fp32 out ----
    moe_gemm<2, 0, false, true>
        <<<dim3(ODIM / BN, TDIM / BM, BDIM), THREADS, SM2>>>(
        cmb_h, cmb_l, y_s, nullptr, out, nullptr, nullptr, b2,
        ECDIM, ODIM, ODIM, ECDIM / BK,
        (long long)TDIM * ECDIM, (long long)ECDIM * ODIM, (long long)TDIM * ODIM,
        0, 0, 1);
}

// round 7
// speedup vs baseline: 2.0735x; 1.5499x over previous
#include <cuda_runtime.h>
#include <cuda_fp16.h>
#include <math.h>
#include <stdint.h>

// ---------------- problem dims ----------------
#define BDIM 4
#define TDIM 2048
#define DDIM 512
#define EDIM 4
#define CDIM 1024
#define HEDIM 512
#define ODIM 512
#define ECDIM 4096
#define EHE (EDIM * HEDIM)   // 2048

typedef __half f16;

// ---------------- operand storage (no cudaMalloc allowed) ----------------
__device__ f16 g_dmT[(size_t)BDIM * ECDIM * TDIM];   // dmask^T single
__device__ f16 g_cmb[(size_t)BDIM * TDIM * ECDIM];   // combine single
__device__ f16 g_x  [(size_t)BDIM * TDIM * DDIM];
__device__ f16 g_w1 [(size_t)EDIM * DDIM * HEDIM];
__device__ f16 g_w2 [(size_t)EDIM * HEDIM * ODIM];   // == [EHE][O]
__device__ f16 g_xd [(size_t)BDIM * ECDIM * DDIM];
__device__ f16 g_h  [(size_t)BDIM * ECDIM * HEDIM];
__device__ f16 g_z  [(size_t)BDIM * TDIM * EHE];     // z = comb_e @ h_e

// ---------------- helpers ----------------
__device__ __forceinline__ uint32_t pack_h2(float a, float b) {
    __half2 p = __floats2half2_rn(a, b);
    return *reinterpret_cast<uint32_t*>(&p);
}

// ---------------- conversion kernels ----------------
__global__ void conv_ew(const float* __restrict__ s, f16* __restrict__ d,
                        long long n4) {
    long long i = (long long)blockIdx.x * blockDim.x + threadIdx.x;
    if (i < n4) {
        float4 v = reinterpret_cast<const float4*>(s)[i];
        uint2 h;
        h.x = pack_h2(v.x, v.y); h.y = pack_h2(v.z, v.w);
        reinterpret_cast<uint2*>(d)[i] = h;
    }
}
// src [R][Cc] per batch -> dst [Cc][R] single fp16
__global__ void tr_one(const float* __restrict__ s, f16* __restrict__ d,
                       int R, int Cc) {
    __shared__ float t[64][33];
    const int c0 = blockIdx.x * 32, r0 = blockIdx.y * 64;
    const size_t zoff = (size_t)blockIdx.z * R * Cc;
    const float* S = s + zoff;
    const int tx = threadIdx.x & 31, ty = threadIdx.x >> 5;
#pragma unroll
    for (int i = 0; i < 8; i++) {
        int r = ty + i * 8;
        t[r][tx] = S[(size_t)(r0 + r) * Cc + c0 + tx];
    }
    __syncthreads();
    const int rr = threadIdx.x >> 3, pair = threadIdx.x & 7;
#pragma unroll
    for (int i = 0; i < 4; i++) {
        int tcol = (pair + i * 8) * 2;
        float a = t[tcol][rr], b = t[tcol + 1][rr];
        size_t o = zoff + (size_t)(c0 + rr) * R + r0 + tcol;
        *reinterpret_cast<uint32_t*>(d + o) = pack_h2(a, b);
    }
}

// ---------------- GEMM tile config ----------------
constexpr int BM = 128, BN = 256, BK = 32;
constexpr int THREADS = 256;
constexpr int OFF_B  = 8192;
constexpr int STAGE  = 24576;
constexpr int NSTG   = 4;
constexpr int SMEM_TOTAL = NSTG * STAGE;   // 96 KB

__device__ __forceinline__ int a_off(int m, int kc) {   // rows 64B
    return m * 64 + ((kc ^ ((m >> 1) & 3)) << 4);
}
__device__ __forceinline__ int b_off(int k, int nc) {   // rows 512B
    return k * 512 + ((nc ^ (k & 7)) << 4);
}
__device__ __forceinline__ uint32_t smem_u32(const void* p) {
    uint32_t a;
    asm("{ .reg .u64 t; cvta.to.shared.u64 t, %1; cvt.u32.u64 %0, t; }"
        : "=r"(a) : "l"(p));
    return a;
}
__device__ __forceinline__ void ldsm4(uint32_t* r, uint32_t addr) {
    asm volatile("ldmatrix.sync.aligned.m8n8.x4.shared.b16 {%0,%1,%2,%3}, [%4];"
                 : "=r"(r[0]), "=r"(r[1]), "=r"(r[2]), "=r"(r[3]) : "r"(addr));
}
__device__ __forceinline__ void ldsm4t(uint32_t* r, uint32_t addr) {
    asm volatile("ldmatrix.sync.aligned.m8n8.x4.trans.shared.b16 {%0,%1,%2,%3}, [%4];"
                 : "=r"(r[0]), "=r"(r[1]), "=r"(r[2]), "=r"(r[3]) : "r"(addr));
}
__device__ __forceinline__ void mma_f16(float* d, const uint32_t* a, const uint32_t* b) {
    asm volatile(
        "mma.sync.aligned.m16n8k16.row.col.f32.f16.f16.f32 "
        "{%0,%1,%2,%3}, {%4,%5,%6,%7}, {%8,%9}, {%0,%1,%2,%3};"
        : "+f"(d[0]), "+f"(d[1]), "+f"(d[2]), "+f"(d[3])
        : "r"(a[0]), "r"(a[1]), "r"(a[2]), "r"(a[3]), "r"(b[0]), "r"(b[1]));
}
__device__ __forceinline__ void cp16(uint32_t dst, const void* src) {
    asm volatile("cp.async.cg.shared.global [%0], [%1], 16;" :: "r"(dst), "l"(src));
}
__device__ __forceinline__ void cp_commit() {
    asm volatile("cp.async.commit_group;" ::: "memory");
}
template<int N>
__device__ __forceinline__ void cp_wait() {
    asm volatile("cp.async.wait_group %0;" :: "n"(N) : "memory");
}

// ---------------- main GEMM kernel ----------------
// CTA 128x256, warp tile 64x64, 1-pass fp16, fp32 accum.
// Two-level z indexing: off = (z/zMod)*s1 + (z%zMod)*s2 for A, B, C, bias.
// OUTM: 0 = fp32 out, 2 = single f16 out.
template<int OUTM, bool GELU_, bool BIAS_>
__global__ __launch_bounds__(THREADS, 1)
void moe_gemm(const f16* __restrict__ Ab, const f16* __restrict__ Bb,
              float* __restrict__ Cf, f16* __restrict__ Ch,
              const float* __restrict__ biasBase,
              int lda, int ldb, int ldc, int KT, int zMod,
              long long sA1, long long sA2, long long sB1, long long sB2,
              long long sC1, long long sC2, long long sBias2)
{
    extern __shared__ char smem[];
    const int tid  = threadIdx.x;
    const int lane = tid & 31;
    const int wid  = tid >> 5;
    const int wm   = (wid & 1) * 64;
    const int wn   = (wid >> 1) * 64;

    const int z = blockIdx.z;
    const int zq = z / zMod, zr = z % zMod;
    const f16* A = Ab + zq * sA1 + zr * sA2;
    const f16* B = Bb + zq * sB1 + zr * sB2;
    const long long coff = zq * sC1 + zr * sC2;
    const float* bias = BIAS_ ? biasBase + zr * sBias2 : nullptr;

    const int m0 = blockIdx.y * BM;
    const int n0 = blockIdx.x * BN;
    const uint32_t sbase = smem_u32(smem);

    float acc[4][8][4];
#pragma unroll
    for (int i = 0; i < 4; i++)
#pragma unroll
        for (int j = 0; j < 8; j++)
#pragma unroll
            for (int c = 0; c < 4; c++) acc[i][j][c] = 0.f;

    auto issue = [&](int it) {
        if (it < KT) {
            const uint32_t st = sbase + (it & (NSTG - 1)) * STAGE;
            const int k0 = it * BK;
#pragma unroll
            for (int i = 0; i < 2; i++) {
                int c = tid + i * THREADS;          // 512 chunks
                int m = c >> 2, kc = c & 3;
                cp16(st + a_off(m, kc),
                     A + (size_t)(m0 + m) * lda + k0 + kc * 8);
            }
#pragma unroll
            for (int i = 0; i < 4; i++) {
                int c = tid + i * THREADS;          // 1024 chunks
                int k = c >> 5, nc = c & 31;
                cp16(st + OFF_B + b_off(k, nc),
                     B + (size_t)(k0 + k) * ldb + n0 + nc * 8);
            }
        }
        cp_commit();
    };

    issue(0); issue(1); issue(2);

    for (int it = 0; it < KT; ++it) {
        cp_wait<2>();
        __syncthreads();
        issue(it + 3);

        const uint32_t cur = sbase + (it & (NSTG - 1)) * STAGE;
#pragma unroll
        for (int kh = 0; kh < 2; kh++) {
            uint32_t ar[4][4];
#pragma unroll
            for (int mf = 0; mf < 4; mf++) {
                int row = wm + mf * 16 + (lane & 15);
                int chunk = kh * 2 + (lane >> 4);
                ldsm4(ar[mf], cur + a_off(row, chunk));
            }
            uint32_t br[4][4];
#pragma unroll
            for (int nb = 0; nb < 4; nb++) {
                int k = kh * 16 + ((lane >> 3) & 1) * 8 + (lane & 7);
                int nchunk = ((wn + nb * 16) >> 3) + (lane >> 4);
                ldsm4t(br[nb], cur + OFF_B + b_off(k, nchunk));
            }
#pragma unroll
            for (int mf = 0; mf < 4; mf++)
#pragma unroll
                for (int nf = 0; nf < 8; nf++)
                    mma_f16(acc[mf][nf], ar[mf], &br[nf >> 1][(nf & 1) * 2]);
        }
    }

    // ---- epilogue ----
    const int g = lane >> 2, t = lane & 3;
#pragma unroll
    for (int mf = 0; mf < 4; mf++) {
#pragma unroll
        for (int nf = 0; nf < 8; nf++) {
            int row = m0 + wm + mf * 16 + g;
            int col = n0 + wn + nf * 8 + t * 2;
            float v0 = acc[mf][nf][0], v1 = acc[mf][nf][1];
            float v2 = acc[mf][nf][2], v3 = acc[mf][nf][3];
            if (BIAS_) {
                float2 bv = *reinterpret_cast<const float2*>(bias + col);
                v0 += bv.x; v1 += bv.y; v2 += bv.x; v3 += bv.y;
            }
            if (GELU_) {
                v0 = 0.5f * v0 * (1.0f + erff(v0 * 0.70710678118654752f));
                v1 = 0.5f * v1 * (1.0f + erff(v1 * 0.70710678118654752f));
                v2 = 0.5f * v2 * (1.0f + erff(v2 * 0.70710678118654752f));
                v3 = 0.5f * v3 * (1.0f + erff(v3 * 0.70710678118654752f));
            }
            size_t o0 = (size_t)(coff + (size_t)row * ldc + col);
            size_t o1 = (size_t)(coff + (size_t)(row + 8) * ldc + col);
            if (OUTM == 0) {
                *reinterpret_cast<float2*>(Cf + o0) = make_float2(v0, v1);
                *reinterpret_cast<float2*>(Cf + o1) = make_float2(v2, v3);
            } else {
                *reinterpret_cast<uint32_t*>(Ch + o0) = pack_h2(v0, v1);
                *reinterpret_cast<uint32_t*>(Ch + o1) = pack_h2(v2, v3);
            }
        }
    }
}

// ---------------- launcher ----------------
extern "C" void kernel_launch(void* const* d_in, const int* in_sizes, int n_in,
                              void* d_out, int out_size)
{
    const float* x     = (const float*)d_in[0];
    const float* dmask = (const float*)d_in[1];
    const float* comb  = (const float*)d_in[2];
    const float* w1    = (const float*)d_in[3];
    const float* b1    = (const float*)d_in[4];
    const float* b2    = (const float*)d_in[6];
    const float* w2f   = (const float*)d_in[5];
    float* out = (float*)d_out;

    f16 *dmT, *cmb, *xs, *w1s, *w2s, *xd, *hh, *zz;
    cudaGetSymbolAddress((void**)&dmT, g_dmT);
    cudaGetSymbolAddress((void**)&cmb, g_cmb);
    cudaGetSymbolAddress((void**)&xs,  g_x);
    cudaGetSymbolAddress((void**)&w1s, g_w1);
    cudaGetSymbolAddress((void**)&w2s, g_w2);
    cudaGetSymbolAddress((void**)&xd,  g_xd);
    cudaGetSymbolAddress((void**)&hh,  g_h);
    cudaGetSymbolAddress((void**)&zz,  g_z);

    cudaFuncSetAttribute(moe_gemm<2, false, false>,
                         cudaFuncAttributeMaxDynamicSharedMemorySize, SMEM_TOTAL);
    cudaFuncSetAttribute(moe_gemm<2, true,  true>,
                         cudaFuncAttributeMaxDynamicSharedMemorySize, SMEM_TOTAL);
    cudaFuncSetAttribute(moe_gemm<0, false, true>,
                         cudaFuncAttributeMaxDynamicSharedMemorySize, SMEM_TOTAL);

    // ---- conversions (all single fp16) ----
    tr_one<<<dim3(ECDIM / 32, TDIM / 64, BDIM), 256>>>(dmask, dmT, TDIM, ECDIM);
    {
        long long n4 = (long long)BDIM * TDIM * ECDIM / 4;
        conv_ew<<<(unsigned)((n4 + 255) / 256), 256>>>(comb, cmb, n4);
    }
    {
        long long n4 = (long long)BDIM * TDIM * DDIM / 4;
        conv_ew<<<(unsigned)((n4 + 255) / 256), 256>>>(x, xs, n4);
    }
    {
        long long n4 = (long long)EDIM * DDIM * HEDIM / 4;
        conv_ew<<<(unsigned)((n4 + 255) / 256), 256>>>(w1, w1s, n4);
        conv_ew<<<(unsigned)((n4 + 255) / 256), 256>>>(w2f, w2s, n4);
    }

    // ---- K1: xd[b][EC][D] = dmT[b][EC][T] @ x[b][T][D] ----
    moe_gemm<2, false, false>
        <<<dim3(DDIM / BN, ECDIM / BM, BDIM), THREADS, SMEM_TOTAL>>>(
        dmT, xs, nullptr, xd, nullptr,
        TDIM, DDIM, DDIM, TDIM / BK, /*zMod*/ 1,
        (long long)ECDIM * TDIM, 0, (long long)TDIM * DDIM, 0,
        (long long)ECDIM * DDIM, 0, 0);

    // ---- K2: h[b][e][C][HE] = gelu(xd_{b,e}[C][D] @ w1_e[D][HE] + b1_e) ----
    moe_gemm<2, true, true>
        <<<dim3(HEDIM / BN, CDIM / BM, BDIM * EDIM), THREADS, SMEM_TOTAL>>>(
        xd, w1s, nullptr, hh, b1,
        DDIM, HEDIM, HEDIM, DDIM / BK, /*zMod*/ EDIM,
        (long long)EDIM * CDIM * DDIM, (long long)CDIM * DDIM,
        0, (long long)DDIM * HEDIM,
        (long long)EDIM * CDIM * HEDIM, (long long)CDIM * HEDIM,
        (long long)HEDIM);

    // ---- K3': z[b][T][e*HE+he] = comb_{b,e}[T][C] @ h_{b,e}[C][HE] ----
    // A = comb[b][t][e*C+c]: lda = ECDIM, offset (b)*T*EC + (e)*C
    moe_gemm<2, false, false>
        <<<dim3(HEDIM / BN, TDIM / BM, BDIM * EDIM), THREADS, SMEM_TOTAL>>>(
        cmb, hh, nullptr, zz, nullptr,
        ECDIM, HEDIM, EHE, CDIM / BK, /*zMod*/ EDIM,
        (long long)TDIM * ECDIM, (long long)CDIM,
        (long long)EDIM * CDIM * HEDIM, (long long)CDIM * HEDIM,
        (long long)TDIM * EHE, (long long)HEDIM,
        0);

    // ---- K4': out[b][T][O] = z[b][T][EHE] @ w2[EHE][O] + b2 ----
    moe_gemm<0, false, true>
        <<<dim3(ODIM / BN, TDIM / BM, BDIM), THREADS, SMEM_TOTAL>>>(
        zz, w2s, out, nullptr, b2,
        EHE, ODIM, ODIM, EHE / BK, /*zMod*/ 1,
        (long long)TDIM * EHE, 0, 0, 0,
        (long long)TDIM * ODIM, 0, 0);
}